// round 1
// baseline (speedup 1.0000x reference)
#include <cuda_runtime.h>

#define NPTS 65536
#define NS 16
#define NPAIR (NPTS*NS)
#define MF 1048576.0f
#define EPS 1e-5f

// ---------------- scratch (device globals; no allocation allowed) ----------------
__device__ float g_xq[NPTS*64];
__device__ float g_xk[NPTS*64];
__device__ float g_xv[NPTS*64];
__device__ float g_prh[3*NPAIR];   // planar [c][pair]
__device__ float g_w1[NPAIR*8];    // [pair][u]
__device__ float g_accP[6];        // sum[3], sumsq[3]
__device__ float g_accW[128];      // sum[64], sumsq[64]
__device__ float g_accU[16];       // sum[8], sumsq[8]

// ---------------- K0: zero accumulators ----------------
__global__ void k_zero() {
    int t = threadIdx.x;
    if (t < 6)   g_accP[t] = 0.f;
    if (t < 128) g_accW[t] = 0.f;
    if (t < 16)  g_accU[t] = 0.f;
}

// ---------------- K1: xq|xk|xv GEMM + pr1 BN stats ----------------
// grid 1024, block 256, dyn smem = (64*192 + 64*65 + 192)*4
__global__ void k1(const float* __restrict__ x, const float* __restrict__ p,
                   const int* __restrict__ idx,
                   const float* __restrict__ Wq, const float* __restrict__ bq,
                   const float* __restrict__ Wk, const float* __restrict__ bk,
                   const float* __restrict__ Wv, const float* __restrict__ bv,
                   const float* __restrict__ Wp1, const float* __restrict__ bp1)
{
    extern __shared__ float sm[];
    float* ws  = sm;                 // [64][192]
    float* xs  = sm + 64*192;        // [64][65]
    float* bsm = xs + 64*65;         // [192]
    int tid = threadIdx.x;
    int base = blockIdx.x * 64;

    for (int i = tid; i < 64*192; i += 256) {
        int k = i / 192, o = i - k*192;
        float v;
        if (o < 64)       v = Wq[k*64 + o];
        else if (o < 128) v = Wk[k*64 + o - 64];
        else              v = Wv[k*64 + o - 128];
        ws[i] = v;
    }
    for (int i = tid; i < 64*64; i += 256) {
        int pt = i >> 6, k = i & 63;
        xs[pt*65 + k] = x[(base + pt)*64 + k];
    }
    if (tid < 192) {
        float v;
        if (tid < 64)       v = bq[tid];
        else if (tid < 128) v = bk[tid - 64];
        else                v = bv[tid - 128];
        bsm[tid] = v;
    }
    __syncthreads();

    int tx = tid & 15, ty = tid >> 4;
    float acc[4][12];
    #pragma unroll
    for (int q = 0; q < 12; q++) {
        float b = bsm[tx*12 + q];
        #pragma unroll
        for (int r = 0; r < 4; r++) acc[r][q] = b;
    }

    #pragma unroll 4
    for (int k = 0; k < 64; k++) {
        float a0 = xs[(ty*4 + 0)*65 + k];
        float a1 = xs[(ty*4 + 1)*65 + k];
        float a2 = xs[(ty*4 + 2)*65 + k];
        float a3 = xs[(ty*4 + 3)*65 + k];
        const float4* wrow = (const float4*)&ws[k*192 + tx*12];
        float4 B0 = wrow[0], B1 = wrow[1], B2 = wrow[2];
        float b[12] = {B0.x,B0.y,B0.z,B0.w, B1.x,B1.y,B1.z,B1.w, B2.x,B2.y,B2.z,B2.w};
        #pragma unroll
        for (int q = 0; q < 12; q++) {
            acc[0][q] += a0 * b[q];
            acc[1][q] += a1 * b[q];
            acc[2][q] += a2 * b[q];
            acc[3][q] += a3 * b[q];
        }
    }

    #pragma unroll
    for (int r = 0; r < 4; r++) {
        int pt = base + ty*4 + r;
        #pragma unroll
        for (int q = 0; q < 12; q++) {
            int o = tx*12 + q;
            float v = acc[r][q];
            if (o < 64)       g_xq[pt*64 + o] = v;
            else if (o < 128) g_xk[pt*64 + o - 64] = v;
            else              g_xv[pt*64 + o - 128] = v;
        }
    }

    // ---- pr1 = rel_p @ Wp1 + bp1 stats over this block's 1024 pairs ----
    float w00 = Wp1[0], w01 = Wp1[1], w02 = Wp1[2];
    float w10 = Wp1[3], w11 = Wp1[4], w12 = Wp1[5];
    float w20 = Wp1[6], w21 = Wp1[7], w22 = Wp1[8];
    float c0 = bp1[0], c1 = bp1[1], c2 = bp1[2];
    float s0=0,s1=0,s2=0,q0=0,q1=0,q2=0;
    for (int t = tid; t < 1024; t += 256) {
        int n = base + (t >> 4);
        int g = idx[n*NS + (t & 15)];
        float r0 = p[g*3+0] - p[n*3+0];
        float r1 = p[g*3+1] - p[n*3+1];
        float r2 = p[g*3+2] - p[n*3+2];
        float v0 = c0 + r0*w00 + r1*w10 + r2*w20;
        float v1 = c1 + r0*w01 + r1*w11 + r2*w21;
        float v2 = c2 + r0*w02 + r1*w12 + r2*w22;
        s0 += v0; s1 += v1; s2 += v2;
        q0 += v0*v0; q1 += v1*v1; q2 += v2*v2;
    }
    #pragma unroll
    for (int off = 16; off; off >>= 1) {
        s0 += __shfl_xor_sync(0xffffffffu, s0, off);
        s1 += __shfl_xor_sync(0xffffffffu, s1, off);
        s2 += __shfl_xor_sync(0xffffffffu, s2, off);
        q0 += __shfl_xor_sync(0xffffffffu, q0, off);
        q1 += __shfl_xor_sync(0xffffffffu, q1, off);
        q2 += __shfl_xor_sync(0xffffffffu, q2, off);
    }
    __syncthreads();   // done reading ws; reuse it as reduction buffer
    int lane = tid & 31, wrp = tid >> 5;
    if (lane == 0) {
        ws[wrp*6+0] = s0; ws[wrp*6+1] = s1; ws[wrp*6+2] = s2;
        ws[wrp*6+3] = q0; ws[wrp*6+4] = q1; ws[wrp*6+5] = q2;
    }
    __syncthreads();
    if (tid < 6) {
        float t2 = 0.f;
        #pragma unroll
        for (int w = 0; w < 8; w++) t2 += ws[w*6 + tid];
        atomicAdd(&g_accP[tid], t2);
    }
}

// ---------------- K2: pr_hat + w-channel BN stats ----------------
// grid 1024, block 256 (64 points / 1024 pairs per block)
__global__ void k2(const float* __restrict__ p, const int* __restrict__ idx,
                   const float* __restrict__ Wp1, const float* __restrict__ bp1,
                   const float* __restrict__ gp, const float* __restrict__ bpbn,
                   const float* __restrict__ Wp2, const float* __restrict__ bp2)
{
    __shared__ float xqs[64*64];
    __shared__ float prhs[3*1024];
    __shared__ int   gix[1024];
    __shared__ float red[256];
    int tid = threadIdx.x, blk = blockIdx.x;
    int pbase = blk * 64;
    int pairbase = blk * 1024;

    for (int i = tid; i < 4096; i += 256) xqs[i] = g_xq[pbase*64 + i];
    for (int i = tid; i < 1024; i += 256) gix[i] = idx[pairbase + i];

    // BN-P constants (redundant per thread; tiny)
    float scP[3], shP[3];
    #pragma unroll
    for (int c = 0; c < 3; c++) {
        float mean = g_accP[c] / MF;
        float var  = g_accP[3+c] / MF - mean*mean;
        float sc   = gp[c] * rsqrtf(var + EPS);
        scP[c] = sc;
        shP[c] = bpbn[c] - mean*sc;
    }
    float w00 = Wp1[0], w01 = Wp1[1], w02 = Wp1[2];
    float w10 = Wp1[3], w11 = Wp1[4], w12 = Wp1[5];
    float w20 = Wp1[6], w21 = Wp1[7], w22 = Wp1[8];
    float c0 = bp1[0], c1 = bp1[1], c2 = bp1[2];
    __syncthreads();

    for (int t = tid; t < 1024; t += 256) {
        int n = pbase + (t >> 4);
        int g = gix[t];
        float r0 = p[g*3+0] - p[n*3+0];
        float r1 = p[g*3+1] - p[n*3+1];
        float r2 = p[g*3+2] - p[n*3+2];
        float v0 = c0 + r0*w00 + r1*w10 + r2*w20;
        float v1 = c1 + r0*w01 + r1*w11 + r2*w21;
        float v2 = c2 + r0*w02 + r1*w12 + r2*w22;
        float h0 = fmaxf(v0*scP[0] + shP[0], 0.f);
        float h1 = fmaxf(v1*scP[1] + shP[1], 0.f);
        float h2 = fmaxf(v2*scP[2] + shP[2], 0.f);
        prhs[t]        = h0;  g_prh[0*NPAIR + pairbase + t] = h0;
        prhs[1024 + t] = h1;  g_prh[1*NPAIR + pairbase + t] = h1;
        prhs[2048 + t] = h2;  g_prh[2*NPAIR + pairbase + t] = h2;
    }
    __syncthreads();

    int c = tid & 63, lane4 = tid >> 6;
    float a0 = Wp2[c], a1 = Wp2[64 + c], a2 = Wp2[128 + c], bb = bp2[c];
    float s = 0.f, ss = 0.f;
    #pragma unroll 4
    for (int t = lane4; t < 1024; t += 4) {
        float pr = bb + prhs[t]*a0 + prhs[1024+t]*a1 + prhs[2048+t]*a2;
        float w  = g_xk[gix[t]*64 + c] - xqs[(t >> 4)*64 + c] + pr;
        s += w; ss += w*w;
    }
    red[tid] = s; __syncthreads();
    if (tid < 64) {
        float t2 = red[tid] + red[64+tid] + red[128+tid] + red[192+tid];
        atomicAdd(&g_accW[tid], t2);
    }
    __syncthreads();
    red[tid] = ss; __syncthreads();
    if (tid < 64) {
        float t2 = red[tid] + red[64+tid] + red[128+tid] + red[192+tid];
        atomicAdd(&g_accW[64 + tid], t2);
    }
}

// ---------------- K3: w1 = relu(bn(w)) @ Ww1 + bw1, store + w1 stats ----------------
// grid 1024, block 256, dyn smem = (4096+3072+8320+512+256)*4 + 1024*4
__global__ void k3(const int* __restrict__ idx,
                   const float* __restrict__ Wp2, const float* __restrict__ bp2,
                   const float* __restrict__ gw1, const float* __restrict__ bw1bn,
                   const float* __restrict__ Ww1, const float* __restrict__ bw1)
{
    extern __shared__ float sm[];
    float* xqs  = sm;               // 4096
    float* prhs = xqs + 4096;       // 3072
    float* whs  = prhs + 3072;      // 128*65 = 8320
    float* ww1  = whs + 8320;       // 512
    float* wred = ww1 + 512;        // 256
    int*   gix  = (int*)(wred + 256); // 1024
    int tid = threadIdx.x, blk = blockIdx.x;
    int pbase = blk*64, pairbase = blk*1024;

    for (int i = tid; i < 4096; i += 256) xqs[i] = g_xq[pbase*64 + i];
    for (int i = tid; i < 3072; i += 256)
        prhs[i] = g_prh[(i >> 10)*NPAIR + pairbase + (i & 1023)];
    for (int i = tid; i < 1024; i += 256) gix[i] = idx[pairbase + i];
    for (int i = tid; i < 512;  i += 256) ww1[i] = Ww1[i];

    int c = tid & 63, lane4 = tid >> 6;
    float mean = g_accW[c] / MF;
    float var  = g_accW[64 + c] / MF - mean*mean;
    float scW  = gw1[c] * rsqrtf(var + EPS);
    float shW  = bw1bn[c] - mean*scW;
    float a0 = Wp2[c], a1 = Wp2[64 + c], a2 = Wp2[128 + c], bb = bp2[c];

    int pp = tid >> 1, half = tid & 1, u0 = half * 4;
    float4 bwv = ((const float4*)bw1)[half];
    float su[4] = {0,0,0,0}, squ[4] = {0,0,0,0};
    __syncthreads();

    for (int ch = 0; ch < 8; ch++) {
        int t0 = ch * 128;
        #pragma unroll 2
        for (int tt = lane4; tt < 128; tt += 4) {
            int t = t0 + tt;
            float pr = bb + prhs[t]*a0 + prhs[1024+t]*a1 + prhs[2048+t]*a2;
            float w  = g_xk[gix[t]*64 + c] - xqs[(t >> 4)*64 + c] + pr;
            whs[tt*65 + c] = fmaxf(w*scW + shW, 0.f);
        }
        __syncthreads();

        float ac0 = bwv.x, ac1 = bwv.y, ac2 = bwv.z, ac3 = bwv.w;
        #pragma unroll 16
        for (int cc = 0; cc < 64; cc++) {
            float a = whs[pp*65 + cc];
            float4 wv = *(const float4*)&ww1[cc*8 + u0];
            ac0 += a*wv.x; ac1 += a*wv.y; ac2 += a*wv.z; ac3 += a*wv.w;
        }
        int t = t0 + pp;
        *(float4*)&g_w1[(pairbase + t)*8 + u0] = make_float4(ac0, ac1, ac2, ac3);
        su[0] += ac0; su[1] += ac1; su[2] += ac2; su[3] += ac3;
        squ[0] += ac0*ac0; squ[1] += ac1*ac1; squ[2] += ac2*ac2; squ[3] += ac3*ac3;
        __syncthreads();
    }

    // reduce across pp within warp (parity-preserving butterfly: offsets 16..2)
    #pragma unroll
    for (int off = 16; off >= 2; off >>= 1) {
        #pragma unroll
        for (int i = 0; i < 4; i++) {
            su[i]  += __shfl_xor_sync(0xffffffffu, su[i],  off);
            squ[i] += __shfl_xor_sync(0xffffffffu, squ[i], off);
        }
    }
    int lane = tid & 31, wrp = tid >> 5;
    if (lane < 2) {
        #pragma unroll
        for (int i = 0; i < 4; i++) {
            wred[wrp*32 + lane*4 + i]     = su[i];
            wred[wrp*32 + 8 + lane*4 + i] = squ[i];
        }
    }
    __syncthreads();
    if (tid < 16) {
        float t2 = 0.f;
        #pragma unroll
        for (int w = 0; w < 8; w++) t2 += wred[w*32 + tid];
        atomicAdd(&g_accU[tid], t2);
    }
}

// ---------------- K4: bn2+relu -> @Ww2 -> softmax(ns) -> aggregate ----------------
// grid 16384, block 256 (4 points per block, 64 threads per point)
__global__ void k4(const int* __restrict__ idx,
                   const float* __restrict__ Wp2, const float* __restrict__ bp2,
                   const float* __restrict__ gw2, const float* __restrict__ bw2bn,
                   const float* __restrict__ Ww2, const float* __restrict__ bw2,
                   float* __restrict__ out)
{
    __shared__ float w1s[4][128];
    __shared__ float hs[4][128];
    __shared__ float w2s[4][128];
    __shared__ float prs[4][48];
    __shared__ int   gix4[4][16];
    __shared__ float wp2s[192], bp2s[64], wws[64], bws[8];
    int tid = threadIdx.x;
    int sub = tid >> 6, ct = tid & 63;
    int n = blockIdx.x*4 + sub;

    for (int i = tid; i < 192; i += 256) wp2s[i] = Wp2[i];
    if (tid < 64) { bp2s[tid] = bp2[tid]; wws[tid] = Ww2[tid]; }
    if (tid < 8)  bws[tid] = bw2[tid];

    w1s[sub][ct]      = g_w1[n*128 + ct];
    w1s[sub][ct + 64] = g_w1[n*128 + ct + 64];
    if (ct < 16) gix4[sub][ct] = idx[n*16 + ct];
    if (ct < 48) prs[sub][ct] = g_prh[(ct >> 4)*NPAIR + n*16 + (ct & 15)];

    int u = ct & 7;
    float mean = g_accU[u] / MF;
    float var  = g_accU[8 + u] / MF - mean*mean;
    float sc2  = gw2[u] * rsqrtf(var + EPS);
    float sh2  = bw2bn[u] - mean*sc2;
    __syncthreads();

    hs[sub][ct]      = fmaxf(w1s[sub][ct]*sc2 + sh2, 0.f);
    hs[sub][ct + 64] = fmaxf(w1s[sub][ct + 64]*sc2 + sh2, 0.f);
    __syncthreads();

    #pragma unroll
    for (int o = ct; o < 128; o += 64) {
        int j = o >> 3, t = o & 7;
        float v = bws[t];
        #pragma unroll
        for (int uu = 0; uu < 8; uu++) v += hs[sub][j*8 + uu] * wws[uu*8 + t];
        w2s[sub][o] = v;
    }
    __syncthreads();

    if (ct < 8) {
        int t = ct;
        float m = -1e30f;
        #pragma unroll
        for (int j = 0; j < 16; j++) m = fmaxf(m, w2s[sub][j*8 + t]);
        float e[16], ssum = 0.f;
        #pragma unroll
        for (int j = 0; j < 16; j++) { e[j] = __expf(w2s[sub][j*8 + t] - m); ssum += e[j]; }
        float inv = 1.f / ssum;
        #pragma unroll
        for (int j = 0; j < 16; j++) w2s[sub][j*8 + t] = e[j] * inv;
    }
    __syncthreads();

    int t = ct & 7;
    float a0 = wp2s[ct], a1 = wp2s[64 + ct], a2 = wp2s[128 + ct], bb = bp2s[ct];
    float acc = 0.f;
    #pragma unroll
    for (int j = 0; j < 16; j++) {
        int g = gix4[sub][j];
        float v = g_xv[g*64 + ct];
        float pr = bb + prs[sub][j]*a0 + prs[sub][16 + j]*a1 + prs[sub][32 + j]*a2;
        acc += (v + pr) * w2s[sub][j*8 + t];
    }
    out[n*64 + ct] = acc;
}

// ---------------- launch ----------------
extern "C" void kernel_launch(void* const* d_in, const int* in_sizes, int n_in,
                              void* d_out, int out_size)
{
    const float* p    = (const float*)d_in[0];
    const float* x    = (const float*)d_in[1];
    const int*   idx  = (const int*)d_in[2];
    const float* Wq   = (const float*)d_in[3];
    const float* bq   = (const float*)d_in[4];
    const float* Wk   = (const float*)d_in[5];
    const float* bk   = (const float*)d_in[6];
    const float* Wv   = (const float*)d_in[7];
    const float* bv   = (const float*)d_in[8];
    const float* Wp1  = (const float*)d_in[9];
    const float* bp1  = (const float*)d_in[10];
    const float* gp   = (const float*)d_in[11];
    const float* bpbn = (const float*)d_in[12];
    const float* Wp2  = (const float*)d_in[13];
    const float* bp2  = (const float*)d_in[14];
    const float* gw1  = (const float*)d_in[15];
    const float* bw1bn= (const float*)d_in[16];
    const float* Ww1  = (const float*)d_in[17];
    const float* bw1  = (const float*)d_in[18];
    const float* gw2  = (const float*)d_in[19];
    const float* bw2bn= (const float*)d_in[20];
    const float* Ww2  = (const float*)d_in[21];
    const float* bw2  = (const float*)d_in[22];
    float* out = (float*)d_out;

    size_t smem1 = (size_t)(64*192 + 64*65 + 192) * 4;             // 66560 B
    size_t smem3 = (size_t)(4096 + 3072 + 8320 + 512 + 256 + 1024) * 4; // 69120 B
    cudaFuncSetAttribute(k1, cudaFuncAttributeMaxDynamicSharedMemorySize, (int)smem1);
    cudaFuncSetAttribute(k3, cudaFuncAttributeMaxDynamicSharedMemorySize, (int)smem3);

    k_zero<<<1, 256>>>();
    k1<<<1024, 256, smem1>>>(x, p, idx, Wq, bq, Wk, bk, Wv, bv, Wp1, bp1);
    k2<<<1024, 256>>>(p, idx, Wp1, bp1, gp, bpbn, Wp2, bp2);
    k3<<<1024, 256, smem3>>>(idx, Wp2, bp2, gw1, bw1bn, Ww1, bw1);
    k4<<<16384, 256>>>(idx, Wp2, bp2, gw2, bw2bn, Ww2, bw2, out);
}

// round 2
// speedup vs baseline: 1.5556x; 1.5556x over previous
#include <cuda_runtime.h>

#define NPTS 65536
#define NS 16
#define NPAIR (NPTS*NS)
#define MF 1048576.0f
#define EPS 1e-5f

// ---------------- scratch ----------------
__device__ float g_xq[NPTS*64];
__device__ float g_xk[NPTS*64];
__device__ float g_xv[NPTS*64];
__device__ float g_prh[3*NPAIR];   // planar [c][pair]
__device__ float g_w1[NPAIR*8];    // [pair][u]
__device__ float g_accP[6];
__device__ float g_accW[128];
__device__ float g_accU[16];

__global__ void k_zero() {
    int t = threadIdx.x;
    if (t < 6)   g_accP[t] = 0.f;
    if (t < 128) g_accW[t] = 0.f;
    if (t < 16)  g_accU[t] = 0.f;
}

// ---------------- K1: qkv GEMM (64 pts/block) + pr1 BN stats ----------------
// weights in smem as float4[64][48]: [k][seg*16+tx] = Wseg[k][tx*4..+3]
__global__ void __launch_bounds__(256) k1(
                   const float* __restrict__ x, const float* __restrict__ p,
                   const int* __restrict__ idx,
                   const float* __restrict__ Wq, const float* __restrict__ bq,
                   const float* __restrict__ Wk, const float* __restrict__ bk,
                   const float* __restrict__ Wv, const float* __restrict__ bv,
                   const float* __restrict__ Wp1, const float* __restrict__ bp1)
{
    extern __shared__ float sm[];
    float4* ws4  = (float4*)sm;            // 64*48 float4 = 48KB
    float*  xs   = sm + 64*48*4;           // 64*68 floats (pad 68)
    float4* bsm4 = (float4*)(xs + 64*68);  // 48 float4
    int tid = threadIdx.x;
    int base = blockIdx.x * 64;

    for (int i = tid; i < 64*48; i += 256) {
        int k = i / 48, r = i - k*48;
        int seg = r >> 4, tx = r & 15;
        const float4* src = (seg == 0) ? (const float4*)Wq :
                            (seg == 1) ? (const float4*)Wk : (const float4*)Wv;
        ws4[i] = src[k*16 + tx];
    }
    {
        float4* xs4 = (float4*)xs;
        for (int i = tid; i < 64*16; i += 256) {
            int pt = i >> 4, kk = i & 15;
            xs4[pt*17 + kk] = ((const float4*)x)[(base + pt)*16 + kk];
        }
    }
    if (tid < 48) {
        int seg = tid >> 4, tx = tid & 15;
        const float4* src = (seg == 0) ? (const float4*)bq :
                            (seg == 1) ? (const float4*)bk : (const float4*)bv;
        bsm4[tid] = src[tx];
    }
    __syncthreads();

    int tx = tid & 15, ty = tid >> 4;
    float4 acc[3][4];
    #pragma unroll
    for (int s = 0; s < 3; s++) {
        float4 b = bsm4[s*16 + tx];
        #pragma unroll
        for (int r = 0; r < 4; r++) acc[s][r] = b;
    }

    #pragma unroll 4
    for (int k = 0; k < 64; k++) {
        float a0 = xs[(ty*4 + 0)*68 + k];
        float a1 = xs[(ty*4 + 1)*68 + k];
        float a2 = xs[(ty*4 + 2)*68 + k];
        float a3 = xs[(ty*4 + 3)*68 + k];
        #pragma unroll
        for (int s = 0; s < 3; s++) {
            float4 w = ws4[k*48 + s*16 + tx];
            acc[s][0].x = fmaf(a0, w.x, acc[s][0].x); acc[s][0].y = fmaf(a0, w.y, acc[s][0].y);
            acc[s][0].z = fmaf(a0, w.z, acc[s][0].z); acc[s][0].w = fmaf(a0, w.w, acc[s][0].w);
            acc[s][1].x = fmaf(a1, w.x, acc[s][1].x); acc[s][1].y = fmaf(a1, w.y, acc[s][1].y);
            acc[s][1].z = fmaf(a1, w.z, acc[s][1].z); acc[s][1].w = fmaf(a1, w.w, acc[s][1].w);
            acc[s][2].x = fmaf(a2, w.x, acc[s][2].x); acc[s][2].y = fmaf(a2, w.y, acc[s][2].y);
            acc[s][2].z = fmaf(a2, w.z, acc[s][2].z); acc[s][2].w = fmaf(a2, w.w, acc[s][2].w);
            acc[s][3].x = fmaf(a3, w.x, acc[s][3].x); acc[s][3].y = fmaf(a3, w.y, acc[s][3].y);
            acc[s][3].z = fmaf(a3, w.z, acc[s][3].z); acc[s][3].w = fmaf(a3, w.w, acc[s][3].w);
        }
    }

    #pragma unroll
    for (int r = 0; r < 4; r++) {
        int pt = base + ty*4 + r;
        ((float4*)&g_xq[pt*64])[tx] = acc[0][r];
        ((float4*)&g_xk[pt*64])[tx] = acc[1][r];
        ((float4*)&g_xv[pt*64])[tx] = acc[2][r];
    }

    // ---- pr1 stats over this block's 1024 pairs ----
    float w00 = Wp1[0], w01 = Wp1[1], w02 = Wp1[2];
    float w10 = Wp1[3], w11 = Wp1[4], w12 = Wp1[5];
    float w20 = Wp1[6], w21 = Wp1[7], w22 = Wp1[8];
    float c0 = bp1[0], c1 = bp1[1], c2 = bp1[2];
    float s0=0,s1=0,s2=0,q0=0,q1=0,q2=0;
    for (int t = tid; t < 1024; t += 256) {
        int n = base + (t >> 4);
        int g = idx[n*NS + (t & 15)];
        float r0 = p[g*3+0] - p[n*3+0];
        float r1 = p[g*3+1] - p[n*3+1];
        float r2 = p[g*3+2] - p[n*3+2];
        float v0 = c0 + r0*w00 + r1*w10 + r2*w20;
        float v1 = c1 + r0*w01 + r1*w11 + r2*w21;
        float v2 = c2 + r0*w02 + r1*w12 + r2*w22;
        s0 += v0; s1 += v1; s2 += v2;
        q0 += v0*v0; q1 += v1*v1; q2 += v2*v2;
    }
    #pragma unroll
    for (int off = 16; off; off >>= 1) {
        s0 += __shfl_xor_sync(0xffffffffu, s0, off);
        s1 += __shfl_xor_sync(0xffffffffu, s1, off);
        s2 += __shfl_xor_sync(0xffffffffu, s2, off);
        q0 += __shfl_xor_sync(0xffffffffu, q0, off);
        q1 += __shfl_xor_sync(0xffffffffu, q1, off);
        q2 += __shfl_xor_sync(0xffffffffu, q2, off);
    }
    __syncthreads();   // done reading ws; reuse as reduction buffer
    float* red = sm;
    int lane = tid & 31, wrp = tid >> 5;
    if (lane == 0) {
        red[wrp*6+0] = s0; red[wrp*6+1] = s1; red[wrp*6+2] = s2;
        red[wrp*6+3] = q0; red[wrp*6+4] = q1; red[wrp*6+5] = q2;
    }
    __syncthreads();
    if (tid < 6) {
        float t2 = 0.f;
        #pragma unroll
        for (int w = 0; w < 8; w++) t2 += red[w*6 + tid];
        atomicAdd(&g_accP[tid], t2);
    }
}

// ---------------- K2: pr_hat store + w-channel BN stats ----------------
// grid 2048, block 256, 512 pairs (32 pts) per block
__global__ void __launch_bounds__(256) k2(
                   const float* __restrict__ p, const int* __restrict__ idx,
                   const float* __restrict__ Wp1, const float* __restrict__ bp1,
                   const float* __restrict__ gp, const float* __restrict__ bpbn,
                   const float* __restrict__ Wp2, const float* __restrict__ bp2)
{
    __shared__ float xqs[32*64];
    __shared__ float prhs[3*512];
    __shared__ int   gix[512];
    __shared__ float red[256], red2[256];
    int tid = threadIdx.x;
    int pair0 = blockIdx.x * 512;
    int pbase = pair0 >> 4;

    for (int i = tid; i < 2048; i += 256) xqs[i] = g_xq[pbase*64 + i];
    for (int i = tid; i < 512;  i += 256) gix[i] = idx[pair0 + i];

    float scP[3], shP[3];
    #pragma unroll
    for (int c = 0; c < 3; c++) {
        float mean = g_accP[c] / MF;
        float var  = g_accP[3+c] / MF - mean*mean;
        float sc   = gp[c] * rsqrtf(var + EPS);
        scP[c] = sc;
        shP[c] = bpbn[c] - mean*sc;
    }
    float w00 = Wp1[0], w01 = Wp1[1], w02 = Wp1[2];
    float w10 = Wp1[3], w11 = Wp1[4], w12 = Wp1[5];
    float w20 = Wp1[6], w21 = Wp1[7], w22 = Wp1[8];
    float c0 = bp1[0], c1 = bp1[1], c2 = bp1[2];
    __syncthreads();

    for (int t = tid; t < 512; t += 256) {
        int n = pbase + (t >> 4);
        int g = gix[t];
        float r0 = p[g*3+0] - p[n*3+0];
        float r1 = p[g*3+1] - p[n*3+1];
        float r2 = p[g*3+2] - p[n*3+2];
        float v0 = c0 + r0*w00 + r1*w10 + r2*w20;
        float v1 = c1 + r0*w01 + r1*w11 + r2*w21;
        float v2 = c2 + r0*w02 + r1*w12 + r2*w22;
        float h0 = fmaxf(v0*scP[0] + shP[0], 0.f);
        float h1 = fmaxf(v1*scP[1] + shP[1], 0.f);
        float h2 = fmaxf(v2*scP[2] + shP[2], 0.f);
        prhs[t]       = h0;  g_prh[0*NPAIR + pair0 + t] = h0;
        prhs[512 + t] = h1;  g_prh[1*NPAIR + pair0 + t] = h1;
        prhs[1024 + t]= h2;  g_prh[2*NPAIR + pair0 + t] = h2;
    }
    __syncthreads();

    int c = tid & 63, lane4 = tid >> 6;
    float a0 = Wp2[c], a1 = Wp2[64 + c], a2 = Wp2[128 + c], bb = bp2[c];
    float s = 0.f, ss = 0.f;
    #pragma unroll 4
    for (int t = lane4; t < 512; t += 4) {
        float pr = fmaf(prhs[1024+t], a2, fmaf(prhs[512+t], a1, fmaf(prhs[t], a0, bb)));
        float w  = __ldg(&g_xk[(size_t)gix[t]*64 + c]) - xqs[(t >> 4)*64 + c] + pr;
        s += w; ss = fmaf(w, w, ss);
    }
    red[tid] = s; red2[tid] = ss;
    __syncthreads();
    if (tid < 64) {
        atomicAdd(&g_accW[tid],      red[tid]  + red[64+tid]  + red[128+tid]  + red[192+tid]);
        atomicAdd(&g_accW[64 + tid], red2[tid] + red2[64+tid] + red2[128+tid] + red2[192+tid]);
    }
}

// ---------------- K3: thread-per-pair, register-resident GEMM ----------------
// grid 4096, block 256 (256 pairs = 16 pts per block)
__global__ void __launch_bounds__(256) k3(
                   const int* __restrict__ idx,
                   const float* __restrict__ Wp2, const float* __restrict__ bp2,
                   const float* __restrict__ gw1, const float* __restrict__ bw1bn,
                   const float* __restrict__ Ww1, const float* __restrict__ bw1)
{
    __shared__ float4 cP[64];     // {wp2_0, wp2_1, wp2_2, bp2}
    __shared__ float2 cS[64];     // {scW, shW}
    __shared__ float4 ww1s[128];  // Ww1[c][0..7] as 2 float4 per c
    __shared__ float  xqs[16*64];
    __shared__ float  bw1s[8];
    __shared__ float  wred[8*16];
    int tid = threadIdx.x;
    int pair0 = blockIdx.x * 256;

    if (tid < 64) {
        int c = tid;
        float mean = g_accW[c] / MF;
        float var  = g_accW[64 + c] / MF - mean*mean;
        float sc   = gw1[c] * rsqrtf(var + EPS);
        cS[c] = make_float2(sc, bw1bn[c] - mean*sc);
        cP[c] = make_float4(Wp2[c], Wp2[64 + c], Wp2[128 + c], bp2[c]);
    } else if (tid < 192) {
        ww1s[tid - 64] = ((const float4*)Ww1)[tid - 64];
    } else if (tid < 200) {
        bw1s[tid - 192] = bw1[tid - 192];
    }
    for (int i = tid; i < 1024; i += 256) xqs[i] = g_xq[(pair0 >> 4)*64 + i];
    __syncthreads();

    int pair = pair0 + tid;
    int g = idx[pair];
    float h0 = g_prh[pair], h1 = g_prh[NPAIR + pair], h2 = g_prh[2*NPAIR + pair];
    const float4* xkr = (const float4*)(g_xk + (size_t)g*64);
    const float*  xqr = &xqs[(tid >> 4)*64];

    float acc[8];
    #pragma unroll
    for (int u = 0; u < 8; u++) acc[u] = bw1s[u];

    #pragma unroll 4
    for (int c4 = 0; c4 < 16; c4++) {
        float4 xk4 = __ldg(&xkr[c4]);
        float xkv[4] = {xk4.x, xk4.y, xk4.z, xk4.w};
        #pragma unroll
        for (int e = 0; e < 4; e++) {
            int c = c4*4 + e;
            float4 a = cP[c];
            float pr = fmaf(h2, a.z, fmaf(h1, a.y, fmaf(h0, a.x, a.w)));
            float w  = xkv[e] - xqr[c] + pr;
            float2 sv = cS[c];
            float wh = fmaxf(fmaf(w, sv.x, sv.y), 0.f);
            float4 u0 = ww1s[2*c], u1 = ww1s[2*c + 1];
            acc[0] = fmaf(wh, u0.x, acc[0]); acc[1] = fmaf(wh, u0.y, acc[1]);
            acc[2] = fmaf(wh, u0.z, acc[2]); acc[3] = fmaf(wh, u0.w, acc[3]);
            acc[4] = fmaf(wh, u1.x, acc[4]); acc[5] = fmaf(wh, u1.y, acc[5]);
            acc[6] = fmaf(wh, u1.z, acc[6]); acc[7] = fmaf(wh, u1.w, acc[7]);
        }
    }

    float4* o = (float4*)(g_w1 + (size_t)pair*8);
    o[0] = make_float4(acc[0], acc[1], acc[2], acc[3]);
    o[1] = make_float4(acc[4], acc[5], acc[6], acc[7]);

    // ---- w1 stats ----
    float st[16];
    #pragma unroll
    for (int u = 0; u < 8; u++) { st[u] = acc[u]; st[8 + u] = acc[u]*acc[u]; }
    #pragma unroll
    for (int off = 16; off; off >>= 1) {
        #pragma unroll
        for (int i = 0; i < 16; i++) st[i] += __shfl_xor_sync(0xffffffffu, st[i], off);
    }
    int lane = tid & 31, wrp = tid >> 5;
    if (lane == 0) {
        #pragma unroll
        for (int i = 0; i < 16; i++) wred[wrp*16 + i] = st[i];
    }
    __syncthreads();
    if (tid < 16) {
        float t2 = 0.f;
        #pragma unroll
        for (int w = 0; w < 8; w++) t2 += wred[w*16 + tid];
        atomicAdd(&g_accU[tid], t2);
    }
}

// ---------------- K4: bn2+relu -> @Ww2 -> softmax(ns) -> aggregate ----------------
__global__ void __launch_bounds__(256) k4(
                   const int* __restrict__ idx,
                   const float* __restrict__ Wp2, const float* __restrict__ bp2,
                   const float* __restrict__ gw2, const float* __restrict__ bw2bn,
                   const float* __restrict__ Ww2, const float* __restrict__ bw2,
                   float* __restrict__ out)
{
    __shared__ float w1s[4][128];
    __shared__ float hs[4][128];
    __shared__ float w2s[4][128];
    __shared__ float prs[4][48];
    __shared__ int   gix4[4][16];
    __shared__ float wp2s[192], bp2s[64], wws[64], bws[8];
    int tid = threadIdx.x;
    int sub = tid >> 6, ct = tid & 63;
    int n = blockIdx.x*4 + sub;

    for (int i = tid; i < 192; i += 256) wp2s[i] = Wp2[i];
    if (tid < 64) { bp2s[tid] = bp2[tid]; wws[tid] = Ww2[tid]; }
    if (tid < 8)  bws[tid] = bw2[tid];

    w1s[sub][ct]      = g_w1[n*128 + ct];
    w1s[sub][ct + 64] = g_w1[n*128 + ct + 64];
    if (ct < 16) gix4[sub][ct] = idx[n*16 + ct];
    if (ct < 48) prs[sub][ct] = g_prh[(ct >> 4)*NPAIR + n*16 + (ct & 15)];

    int u = ct & 7;
    float mean = g_accU[u] / MF;
    float var  = g_accU[8 + u] / MF - mean*mean;
    float sc2  = gw2[u] * rsqrtf(var + EPS);
    float sh2  = bw2bn[u] - mean*sc2;
    __syncthreads();

    hs[sub][ct]      = fmaxf(w1s[sub][ct]*sc2 + sh2, 0.f);
    hs[sub][ct + 64] = fmaxf(w1s[sub][ct + 64]*sc2 + sh2, 0.f);
    __syncthreads();

    #pragma unroll
    for (int o = ct; o < 128; o += 64) {
        int j = o >> 3, t = o & 7;
        float v = bws[t];
        #pragma unroll
        for (int uu = 0; uu < 8; uu++) v += hs[sub][j*8 + uu] * wws[uu*8 + t];
        w2s[sub][o] = v;
    }
    __syncthreads();

    if (ct < 8) {
        int t = ct;
        float m = -1e30f;
        #pragma unroll
        for (int j = 0; j < 16; j++) m = fmaxf(m, w2s[sub][j*8 + t]);
        float e[16], ssum = 0.f;
        #pragma unroll
        for (int j = 0; j < 16; j++) { e[j] = __expf(w2s[sub][j*8 + t] - m); ssum += e[j]; }
        float inv = 1.f / ssum;
        #pragma unroll
        for (int j = 0; j < 16; j++) w2s[sub][j*8 + t] = e[j] * inv;
    }
    __syncthreads();

    int t = ct & 7;
    float a0 = wp2s[ct], a1 = wp2s[64 + ct], a2 = wp2s[128 + ct], bb = bp2s[ct];
    float acc = 0.f;
    #pragma unroll
    for (int j = 0; j < 16; j++) {
        int g = gix4[sub][j];
        float v = g_xv[(size_t)g*64 + ct];
        float pr = fmaf(prs[sub][32 + j], a2, fmaf(prs[sub][16 + j], a1, fmaf(prs[sub][j], a0, bb)));
        acc += (v + pr) * w2s[sub][j*8 + t];
    }
    out[n*64 + ct] = acc;
}

// ---------------- launch ----------------
extern "C" void kernel_launch(void* const* d_in, const int* in_sizes, int n_in,
                              void* d_out, int out_size)
{
    const float* p    = (const float*)d_in[0];
    const float* x    = (const float*)d_in[1];
    const int*   idx  = (const int*)d_in[2];
    const float* Wq   = (const float*)d_in[3];
    const float* bq   = (const float*)d_in[4];
    const float* Wk   = (const float*)d_in[5];
    const float* bk   = (const float*)d_in[6];
    const float* Wv   = (const float*)d_in[7];
    const float* bv   = (const float*)d_in[8];
    const float* Wp1  = (const float*)d_in[9];
    const float* bp1  = (const float*)d_in[10];
    const float* gp   = (const float*)d_in[11];
    const float* bpbn = (const float*)d_in[12];
    const float* Wp2  = (const float*)d_in[13];
    const float* bp2  = (const float*)d_in[14];
    const float* gw1  = (const float*)d_in[15];
    const float* bw1bn= (const float*)d_in[16];
    const float* Ww1  = (const float*)d_in[17];
    const float* bw1  = (const float*)d_in[18];
    const float* gw2  = (const float*)d_in[19];
    const float* bw2bn= (const float*)d_in[20];
    const float* Ww2  = (const float*)d_in[21];
    const float* bw2  = (const float*)d_in[22];
    float* out = (float*)d_out;

    size_t smem1 = (size_t)(64*48*4 + 64*68 + 48*4) * 4;  // ~67KB
    cudaFuncSetAttribute(k1, cudaFuncAttributeMaxDynamicSharedMemorySize, (int)smem1);

    k_zero<<<1, 256>>>();
    k1<<<1024, 256, smem1>>>(x, p, idx, Wq, bq, Wk, bk, Wv, bv, Wp1, bp1);
    k2<<<2048, 256>>>(p, idx, Wp1, bp1, gp, bpbn, Wp2, bp2);
    k3<<<4096, 256>>>(idx, Wp2, bp2, gw1, bw1bn, Ww1, bw1);
    k4<<<16384, 256>>>(idx, Wp2, bp2, gw2, bw2bn, Ww2, bw2, out);
}

// round 3
// speedup vs baseline: 1.5682x; 1.0081x over previous
#include <cuda_runtime.h>

#define NPTS 65536
#define NS 16
#define NPAIR (NPTS*NS)
#define MF 1048576.0f
#define EPS 1e-5f

typedef unsigned long long ull;

__device__ __forceinline__ ull ffma2(ull a, ull b, ull c) {
    ull d; asm("fma.rn.f32x2 %0,%1,%2,%3;" : "=l"(d) : "l"(a), "l"(b), "l"(c)); return d;
}
__device__ __forceinline__ ull fadd2(ull a, ull b) {
    ull d; asm("add.rn.f32x2 %0,%1,%2;" : "=l"(d) : "l"(a), "l"(b)); return d;
}
__device__ __forceinline__ ull pack2(float lo, float hi) {
    ull d; asm("mov.b64 %0,{%1,%2};" : "=l"(d) : "f"(lo), "f"(hi)); return d;
}
__device__ __forceinline__ void unpack2(ull v, float& lo, float& hi) {
    asm("mov.b64 {%0,%1},%2;" : "=f"(lo), "=f"(hi) : "l"(v));
}

// ---------------- scratch ----------------
__device__ float g_xq[NPTS*64];
__device__ float g_xk[NPTS*64];
__device__ float g_xv[NPTS*64];
__device__ float g_prh[3*NPAIR];   // planar [c][pair]
__device__ float g_w1[NPAIR*8];
__device__ float g_accP[6];
__device__ float g_accW[128];
__device__ float g_accU[16];

__global__ void k_zero() {
    int t = threadIdx.x;
    if (t < 6)   g_accP[t] = 0.f;
    if (t < 128) g_accW[t] = 0.f;
    if (t < 16)  g_accU[t] = 0.f;
}

// ---------------- K1: qkv GEMM (64 pts/block) + pr1 BN stats ----------------
__global__ void __launch_bounds__(256) k1(
                   const float* __restrict__ x, const float* __restrict__ p,
                   const int* __restrict__ idx,
                   const float* __restrict__ Wq, const float* __restrict__ bq,
                   const float* __restrict__ Wk, const float* __restrict__ bk,
                   const float* __restrict__ Wv, const float* __restrict__ bv,
                   const float* __restrict__ Wp1, const float* __restrict__ bp1)
{
    extern __shared__ float sm[];
    float4* ws4  = (float4*)sm;            // [64][48] float4
    float*  xs   = sm + 64*48*4;           // [64][68]
    float4* bsm4 = (float4*)(xs + 64*68);  // [48]
    int tid = threadIdx.x;
    int base = blockIdx.x * 64;

    for (int i = tid; i < 64*48; i += 256) {
        int k = i / 48, r = i - k*48;
        int seg = r >> 4, tx = r & 15;
        const float4* src = (seg == 0) ? (const float4*)Wq :
                            (seg == 1) ? (const float4*)Wk : (const float4*)Wv;
        ws4[i] = src[k*16 + tx];
    }
    {
        float4* xs4 = (float4*)xs;
        for (int i = tid; i < 64*16; i += 256) {
            int pt = i >> 4, kk = i & 15;
            xs4[pt*17 + kk] = ((const float4*)x)[(base + pt)*16 + kk];
        }
    }
    if (tid < 48) {
        int seg = tid >> 4, tx = tid & 15;
        const float4* src = (seg == 0) ? (const float4*)bq :
                            (seg == 1) ? (const float4*)bk : (const float4*)bv;
        bsm4[tid] = src[tx];
    }
    __syncthreads();

    int tx = tid & 15, ty = tid >> 4;
    ulonglong2 acc[3][4];
    #pragma unroll
    for (int s = 0; s < 3; s++) {
        ulonglong2 b = ((ulonglong2*)bsm4)[s*16 + tx];
        #pragma unroll
        for (int r = 0; r < 4; r++) acc[s][r] = b;
    }

    #pragma unroll 4
    for (int kq = 0; kq < 16; kq++) {
        float4 aq[4];
        #pragma unroll
        for (int r = 0; r < 4; r++) aq[r] = *(float4*)&xs[(ty*4 + r)*68 + kq*4];
        #pragma unroll
        for (int e = 0; e < 4; e++) {
            int k = kq*4 + e;
            ull ap[4];
            #pragma unroll
            for (int r = 0; r < 4; r++) {
                float av = ((float*)&aq[r])[e];
                ap[r] = pack2(av, av);
            }
            #pragma unroll
            for (int s = 0; s < 3; s++) {
                ulonglong2 w2 = *(ulonglong2*)&ws4[k*48 + s*16 + tx];
                #pragma unroll
                for (int r = 0; r < 4; r++) {
                    acc[s][r].x = ffma2(ap[r], w2.x, acc[s][r].x);
                    acc[s][r].y = ffma2(ap[r], w2.y, acc[s][r].y);
                }
            }
        }
    }

    #pragma unroll
    for (int r = 0; r < 4; r++) {
        int pt = base + ty*4 + r;
        ((ulonglong2*)&g_xq[pt*64])[tx] = acc[0][r];
        ((ulonglong2*)&g_xk[pt*64])[tx] = acc[1][r];
        ((ulonglong2*)&g_xv[pt*64])[tx] = acc[2][r];
    }

    // ---- pr1 stats over this block's 1024 pairs ----
    float w00 = Wp1[0], w01 = Wp1[1], w02 = Wp1[2];
    float w10 = Wp1[3], w11 = Wp1[4], w12 = Wp1[5];
    float w20 = Wp1[6], w21 = Wp1[7], w22 = Wp1[8];
    float c0 = bp1[0], c1 = bp1[1], c2 = bp1[2];
    float s0=0,s1=0,s2=0,q0=0,q1=0,q2=0;
    for (int t = tid; t < 1024; t += 256) {
        int n = base + (t >> 4);
        int g = idx[n*NS + (t & 15)];
        float r0 = p[g*3+0] - p[n*3+0];
        float r1 = p[g*3+1] - p[n*3+1];
        float r2 = p[g*3+2] - p[n*3+2];
        float v0 = c0 + r0*w00 + r1*w10 + r2*w20;
        float v1 = c1 + r0*w01 + r1*w11 + r2*w21;
        float v2 = c2 + r0*w02 + r1*w12 + r2*w22;
        s0 += v0; s1 += v1; s2 += v2;
        q0 += v0*v0; q1 += v1*v1; q2 += v2*v2;
    }
    #pragma unroll
    for (int off = 16; off; off >>= 1) {
        s0 += __shfl_xor_sync(0xffffffffu, s0, off);
        s1 += __shfl_xor_sync(0xffffffffu, s1, off);
        s2 += __shfl_xor_sync(0xffffffffu, s2, off);
        q0 += __shfl_xor_sync(0xffffffffu, q0, off);
        q1 += __shfl_xor_sync(0xffffffffu, q1, off);
        q2 += __shfl_xor_sync(0xffffffffu, q2, off);
    }
    __syncthreads();
    float* red = sm;
    int lane = tid & 31, wrp = tid >> 5;
    if (lane == 0) {
        red[wrp*6+0] = s0; red[wrp*6+1] = s1; red[wrp*6+2] = s2;
        red[wrp*6+3] = q0; red[wrp*6+4] = q1; red[wrp*6+5] = q2;
    }
    __syncthreads();
    if (tid < 6) {
        float t2 = 0.f;
        #pragma unroll
        for (int w = 0; w < 8; w++) t2 += red[w*6 + tid];
        atomicAdd(&g_accP[tid], t2);
    }
}

// ---------------- K2: pr_hat + w-channel BN stats ----------------
// grid 1024, block 256: 64 points = 1024 pairs per block
__global__ void __launch_bounds__(256) k2(
                   const float* __restrict__ p, const int* __restrict__ idx,
                   const float* __restrict__ Wp1, const float* __restrict__ bp1,
                   const float* __restrict__ gp, const float* __restrict__ bpbn,
                   const float* __restrict__ Wp2, const float* __restrict__ bp2)
{
    __shared__ float4 prh4[1024];     // {h0,h1,h2,0} per pair
    __shared__ float  xqn[64*64];     // -xq
    __shared__ int    gixs[1024];
    __shared__ float  sred[1024];     // [16 quads][8 warps][8 vals]
    int tid = threadIdx.x;
    int pair0 = blockIdx.x * 1024;
    int pbase = pair0 >> 4;

    for (int i = tid; i < 1024; i += 256) gixs[i] = idx[pair0 + i];
    for (int i = tid; i < 4096; i += 256) xqn[i] = -g_xq[pbase*64 + i];

    float scP[3], shP[3];
    #pragma unroll
    for (int c = 0; c < 3; c++) {
        float mean = g_accP[c] / MF;
        float var  = g_accP[3+c] / MF - mean*mean;
        float sc   = gp[c] * rsqrtf(var + EPS);
        scP[c] = sc;
        shP[c] = bpbn[c] - mean*sc;
    }
    float w00 = Wp1[0], w01 = Wp1[1], w02 = Wp1[2];
    float w10 = Wp1[3], w11 = Wp1[4], w12 = Wp1[5];
    float w20 = Wp1[6], w21 = Wp1[7], w22 = Wp1[8];
    float c0 = bp1[0], c1 = bp1[1], c2 = bp1[2];
    __syncthreads();

    // phase A: compute prh, store planar gmem + smem tile
    #pragma unroll
    for (int kk = 0; kk < 4; kk++) {
        int t = tid + kk*256;
        int n = pbase + (t >> 4);
        int g = gixs[t];
        float r0 = p[g*3+0] - p[n*3+0];
        float r1 = p[g*3+1] - p[n*3+1];
        float r2 = p[g*3+2] - p[n*3+2];
        float v0 = c0 + r0*w00 + r1*w10 + r2*w20;
        float v1 = c1 + r0*w01 + r1*w11 + r2*w21;
        float v2 = c2 + r0*w02 + r1*w12 + r2*w22;
        float h0 = fmaxf(v0*scP[0] + shP[0], 0.f);
        float h1 = fmaxf(v1*scP[1] + shP[1], 0.f);
        float h2 = fmaxf(v2*scP[2] + shP[2], 0.f);
        prh4[t] = make_float4(h0, h1, h2, 0.f);
        g_prh[0*NPAIR + pair0 + t] = h0;
        g_prh[1*NPAIR + pair0 + t] = h1;
        g_prh[2*NPAIR + pair0 + t] = h2;
    }
    __syncthreads();

    // phase B: w stats; thread = (pair-lane tid>>4, channel-quad tid&15)
    int cq = (tid & 15) * 4;
    float4 A0q = __ldg((const float4*)&Wp2[cq]);
    float4 A1q = __ldg((const float4*)&Wp2[64 + cq]);
    float4 A2q = __ldg((const float4*)&Wp2[128 + cq]);
    float4 Bq  = __ldg((const float4*)&bp2[cq]);
    ulonglong2 A0u = *(ulonglong2*)&A0q, A1u = *(ulonglong2*)&A1q;
    ulonglong2 A2u = *(ulonglong2*)&A2q, Bu  = *(ulonglong2*)&Bq;

    ull s_lo = 0, s_hi = 0, ss_lo = 0, ss_hi = 0;
    int pl = tid >> 4;
    #pragma unroll 4
    for (int k = 0; k < 64; k++) {
        int t = pl + 16*k;
        int g = gixs[t];
        float4 xk4 = __ldg((const float4*)&g_xk[(size_t)g*64 + cq]);
        float4 h4 = prh4[t];
        ull h0p = pack2(h4.x, h4.x), h1p = pack2(h4.y, h4.y), h2p = pack2(h4.z, h4.z);
        ulonglong2 xku = *(ulonglong2*)&xk4;
        ulonglong2 xqu = *(ulonglong2*)&xqn[(t >> 4)*64 + cq];
        ull t_lo = ffma2(h2p, A2u.x, ffma2(h1p, A1u.x, ffma2(h0p, A0u.x, Bu.x)));
        ull t_hi = ffma2(h2p, A2u.y, ffma2(h1p, A1u.y, ffma2(h0p, A0u.y, Bu.y)));
        ull w_lo = fadd2(xku.x, fadd2(xqu.x, t_lo));
        ull w_hi = fadd2(xku.y, fadd2(xqu.y, t_hi));
        s_lo = fadd2(s_lo, w_lo); s_hi = fadd2(s_hi, w_hi);
        ss_lo = ffma2(w_lo, w_lo, ss_lo); ss_hi = ffma2(w_hi, w_hi, ss_hi);
    }

    float v[8];
    unpack2(s_lo, v[0], v[1]); unpack2(s_hi, v[2], v[3]);
    unpack2(ss_lo, v[4], v[5]); unpack2(ss_hi, v[6], v[7]);
    #pragma unroll
    for (int i = 0; i < 8; i++) v[i] += __shfl_xor_sync(0xffffffffu, v[i], 16);
    int lane = tid & 31, wrp = tid >> 5;
    if (lane < 16) {
        #pragma unroll
        for (int i = 0; i < 8; i++) sred[lane*64 + wrp*8 + i] = v[i];
    }
    __syncthreads();
    if (tid < 128) {
        int q = tid >> 3, vi = tid & 7;
        float s = 0.f;
        #pragma unroll
        for (int w = 0; w < 8; w++) s += sred[q*64 + w*8 + vi];
        int gi = (vi < 4) ? (q*4 + vi) : (64 + q*4 + vi - 4);
        atomicAdd(&g_accW[gi], s);
    }
}

// ---------------- K3: staged coalesced gather + reg GEMM (f32x2) ----------------
// grid 8192, block 128: 128 pairs = 8 points per block
__global__ void __launch_bounds__(128) k3(
                   const int* __restrict__ idx,
                   const float* __restrict__ Wp2, const float* __restrict__ bp2,
                   const float* __restrict__ gw1, const float* __restrict__ bw1bn,
                   const float* __restrict__ Ww1, const float* __restrict__ bw1)
{
    __shared__ float rows[128*68];   // xk * sc, per pair, padded
    __shared__ float xqn[8*64];      // -xq * sc
    __shared__ float sA0[64], sA1[64], sA2[64], sB[64], sS[64];
    __shared__ float sW[512];        // Ww1[c][u]
    __shared__ int   gixs[128];
    __shared__ float wred[4*16];
    int tid = threadIdx.x;
    int pair0 = blockIdx.x * 128;
    int pbase = pair0 >> 4;

    if (tid < 64) {
        int c = tid;
        float mean = g_accW[c] / MF;
        float var  = g_accW[64 + c] / MF - mean*mean;
        float sc   = gw1[c] * rsqrtf(var + EPS);
        float sh   = bw1bn[c] - mean*sc;
        sS[c]  = sc;
        sA0[c] = Wp2[c] * sc;
        sA1[c] = Wp2[64 + c] * sc;
        sA2[c] = Wp2[128 + c] * sc;
        sB[c]  = bp2[c] * sc + sh;
    }
    if (tid < 128) gixs[tid] = idx[pair0 + tid];
    for (int i = tid; i < 512; i += 128) sW[i] = Ww1[i];

    int pair = pair0 + tid;
    float h0 = g_prh[pair], h1 = g_prh[NPAIR + pair], h2 = g_prh[2*NPAIR + pair];
    float bw[8];
    #pragma unroll
    for (int u = 0; u < 8; u++) bw[u] = __ldg(&bw1[u]);
    __syncthreads();

    // -xq * sc tile
    #pragma unroll
    for (int kk = 0; kk < 4; kk++) {
        int i = tid + kk*128;
        int c = i & 63;
        xqn[i] = -g_xq[pbase*64 + i] * sS[c];
    }
    // stage xk rows, scaled: warp per row, lane = 2 channels
    int lane = tid & 31, wrp = tid >> 5;
    float s2x = sS[2*lane], s2y = sS[2*lane + 1];
    for (int r = wrp; r < 128; r += 4) {
        int g = gixs[r];
        float2 v = __ldg((const float2*)g_xk + (size_t)g*32 + lane);
        v.x *= s2x; v.y *= s2y;
        *(float2*)&rows[r*68 + lane*2] = v;
    }
    __syncthreads();

    ull h0p = pack2(h0, h0), h1p = pack2(h1, h1), h2p = pack2(h2, h2);
    ull acc0 = pack2(bw[0], bw[1]), acc1 = pack2(bw[2], bw[3]);
    ull acc2_ = pack2(bw[4], bw[5]), acc3 = pack2(bw[6], bw[7]);
    const float* xqr = &xqn[(tid >> 4)*64];
    const float* rowr = &rows[tid*68];

    #pragma unroll
    for (int c4 = 0; c4 < 16; c4++) {
        ulonglong2 xku = *(ulonglong2*)&rowr[c4*4];
        ulonglong2 xqu = *(ulonglong2*)&xqr[c4*4];
        ulonglong2 A0u = *(ulonglong2*)&sA0[c4*4];
        ulonglong2 A1u = *(ulonglong2*)&sA1[c4*4];
        ulonglong2 A2u = *(ulonglong2*)&sA2[c4*4];
        ulonglong2 Bu  = *(ulonglong2*)&sB[c4*4];
        ull t_lo = ffma2(h2p, A2u.x, ffma2(h1p, A1u.x, ffma2(h0p, A0u.x, Bu.x)));
        ull t_hi = ffma2(h2p, A2u.y, ffma2(h1p, A1u.y, ffma2(h0p, A0u.y, Bu.y)));
        ull w_lo = fadd2(xku.x, fadd2(xqu.x, t_lo));
        ull w_hi = fadd2(xku.y, fadd2(xqu.y, t_hi));
        float w0, w1, w2, w3;
        unpack2(w_lo, w0, w1); unpack2(w_hi, w2, w3);
        float wh[4] = {fmaxf(w0,0.f), fmaxf(w1,0.f), fmaxf(w2,0.f), fmaxf(w3,0.f)};
        #pragma unroll
        for (int e = 0; e < 4; e++) {
            int c = c4*4 + e;
            ull whp = pack2(wh[e], wh[e]);
            ulonglong2 W0 = *(ulonglong2*)&sW[c*8];
            ulonglong2 W1 = *(ulonglong2*)&sW[c*8 + 4];
            acc0 = ffma2(whp, W0.x, acc0);
            acc1 = ffma2(whp, W0.y, acc1);
            acc2_ = ffma2(whp, W1.x, acc2_);
            acc3 = ffma2(whp, W1.y, acc3);
        }
    }

    float a[8];
    unpack2(acc0, a[0], a[1]); unpack2(acc1, a[2], a[3]);
    unpack2(acc2_, a[4], a[5]); unpack2(acc3, a[6], a[7]);
    float4* o = (float4*)(g_w1 + (size_t)pair*8);
    o[0] = make_float4(a[0], a[1], a[2], a[3]);
    o[1] = make_float4(a[4], a[5], a[6], a[7]);

    // ---- w1 stats ----
    float st[16];
    #pragma unroll
    for (int u = 0; u < 8; u++) { st[u] = a[u]; st[8 + u] = a[u]*a[u]; }
    #pragma unroll
    for (int off = 16; off; off >>= 1) {
        #pragma unroll
        for (int i = 0; i < 16; i++) st[i] += __shfl_xor_sync(0xffffffffu, st[i], off);
    }
    if (lane == 0) {
        #pragma unroll
        for (int i = 0; i < 16; i++) wred[wrp*16 + i] = st[i];
    }
    __syncthreads();
    if (tid < 16) {
        float t2 = wred[tid] + wred[16 + tid] + wred[32 + tid] + wred[48 + tid];
        atomicAdd(&g_accU[tid], t2);
    }
}

// ---------------- K4: bn2+relu -> @Ww2 -> softmax(ns) -> aggregate ----------------
__global__ void __launch_bounds__(256) k4(
                   const int* __restrict__ idx,
                   const float* __restrict__ Wp2, const float* __restrict__ bp2,
                   const float* __restrict__ gw2, const float* __restrict__ bw2bn,
                   const float* __restrict__ Ww2, const float* __restrict__ bw2,
                   float* __restrict__ out)
{
    __shared__ float w1s[4][128];
    __shared__ float hs[4][128];
    __shared__ float w2s[4][128];
    __shared__ float prs[4][48];
    __shared__ int   gix4[4][16];
    __shared__ float wp2s[192], bp2s[64], wws[64], bws[8];
    int tid = threadIdx.x;
    int sub = tid >> 6, ct = tid & 63;
    int n = blockIdx.x*4 + sub;

    for (int i = tid; i < 192; i += 256) wp2s[i] = Wp2[i];
    if (tid < 64) { bp2s[tid] = bp2[tid]; wws[tid] = Ww2[tid]; }
    if (tid < 8)  bws[tid] = bw2[tid];

    w1s[sub][ct]      = g_w1[n*128 + ct];
    w1s[sub][ct + 64] = g_w1[n*128 + ct + 64];
    if (ct < 16) gix4[sub][ct] = idx[n*16 + ct];
    if (ct < 48) prs[sub][ct] = g_prh[(ct >> 4)*NPAIR + n*16 + (ct & 15)];

    int u = ct & 7;
    float mean = g_accU[u] / MF;
    float var  = g_accU[8 + u] / MF - mean*mean;
    float sc2  = gw2[u] * rsqrtf(var + EPS);
    float sh2  = bw2bn[u] - mean*sc2;
    __syncthreads();

    hs[sub][ct]      = fmaxf(w1s[sub][ct]*sc2 + sh2, 0.f);
    hs[sub][ct + 64] = fmaxf(w1s[sub][ct + 64]*sc2 + sh2, 0.f);
    __syncthreads();

    #pragma unroll
    for (int o = ct; o < 128; o += 64) {
        int j = o >> 3, t = o & 7;
        float v = bws[t];
        #pragma unroll
        for (int uu = 0; uu < 8; uu++) v += hs[sub][j*8 + uu] * wws[uu*8 + t];
        w2s[sub][o] = v;
    }
    __syncthreads();

    if (ct < 8) {
        int t = ct;
        float m = -1e30f;
        #pragma unroll
        for (int j = 0; j < 16; j++) m = fmaxf(m, w2s[sub][j*8 + t]);
        float e[16], ssum = 0.f;
        #pragma unroll
        for (int j = 0; j < 16; j++) { e[j] = __expf(w2s[sub][j*8 + t] - m); ssum += e[j]; }
        float inv = 1.f / ssum;
        #pragma unroll
        for (int j = 0; j < 16; j++) w2s[sub][j*8 + t] = e[j] * inv;
    }
    __syncthreads();

    int t = ct & 7;
    float a0 = wp2s[ct], a1 = wp2s[64 + ct], a2 = wp2s[128 + ct], bb = bp2s[ct];
    float acc = 0.f;
    #pragma unroll
    for (int j = 0; j < 16; j++) {
        int g = gix4[sub][j];
        float v = g_xv[(size_t)g*64 + ct];
        float pr = fmaf(prs[sub][32 + j], a2, fmaf(prs[sub][16 + j], a1, fmaf(prs[sub][j], a0, bb)));
        acc += (v + pr) * w2s[sub][j*8 + t];
    }
    out[n*64 + ct] = acc;
}

// ---------------- launch ----------------
extern "C" void kernel_launch(void* const* d_in, const int* in_sizes, int n_in,
                              void* d_out, int out_size)
{
    const float* p    = (const float*)d_in[0];
    const float* x    = (const float*)d_in[1];
    const int*   idx  = (const int*)d_in[2];
    const float* Wq   = (const float*)d_in[3];
    const float* bq   = (const float*)d_in[4];
    const float* Wk   = (const float*)d_in[5];
    const float* bk   = (const float*)d_in[6];
    const float* Wv   = (const float*)d_in[7];
    const float* bv   = (const float*)d_in[8];
    const float* Wp1  = (const float*)d_in[9];
    const float* bp1  = (const float*)d_in[10];
    const float* gp   = (const float*)d_in[11];
    const float* bpbn = (const float*)d_in[12];
    const float* Wp2  = (const float*)d_in[13];
    const float* bp2  = (const float*)d_in[14];
    const float* gw1  = (const float*)d_in[15];
    const float* bw1bn= (const float*)d_in[16];
    const float* Ww1  = (const float*)d_in[17];
    const float* bw1  = (const float*)d_in[18];
    const float* gw2  = (const float*)d_in[19];
    const float* bw2bn= (const float*)d_in[20];
    const float* Ww2  = (const float*)d_in[21];
    const float* bw2  = (const float*)d_in[22];
    float* out = (float*)d_out;

    size_t smem1 = (size_t)(64*48*4 + 64*68 + 48*4) * 4;  // ~66KB
    cudaFuncSetAttribute(k1, cudaFuncAttributeMaxDynamicSharedMemorySize, (int)smem1);

    k_zero<<<1, 256>>>();
    k1<<<1024, 256, smem1>>>(x, p, idx, Wq, bq, Wk, bk, Wv, bv, Wp1, bp1);
    k2<<<1024, 256>>>(p, idx, Wp1, bp1, gp, bpbn, Wp2, bp2);
    k3<<<8192, 128>>>(idx, Wp2, bp2, gw1, bw1bn, Ww1, bw1);
    k4<<<16384, 256>>>(idx, Wp2, bp2, gw2, bw2bn, Ww2, bw2, out);
}